// round 1
// baseline (speedup 1.0000x reference)
#include <cuda_runtime.h>
#include <cuda_bf16.h>

// GHM-C loss, single-pass formulation.
// loss = -(sum_b w[b]*S[b]) / tot
//   count[b] = #valid elements with bin(g)==b          (g = |pred - pos|)
//   S[b]     = sum over those elements of (pos ? log(pred) : log(1-pred)*(1-hm)^4)
//   tot      = max(sum_b count[b], 1)
//   w[b]     = (count[b]>0 ? tot/max(count[b],1) : 0) / max(#nonempty bins, 1)
// The num_pos==0 branch of the reference is identical to the general branch
// (pos_loss is exactly 0 in that case), so it needs no special handling.

#define HW_BITS 18          // 512*512 = 2^18
#define HW (1 << HW_BITS)
#define NBINS 10

__device__ float g_cnt[NBINS];
__device__ float g_sum[NBINS];

__global__ void ghm_zero_kernel() {
    if (threadIdx.x < NBINS) {
        g_cnt[threadIdx.x] = 0.0f;
        g_sum[threadIdx.x] = 0.0f;
    }
}

__global__ __launch_bounds__(256) void ghm_main_kernel(
    const float* __restrict__ pred,
    const float* __restrict__ target,
    int n4)   // number of float4 groups (n/4)
{
    float cnt[NBINS];
    float s[NBINS];
#pragma unroll
    for (int b = 0; b < NBINS; b++) { cnt[b] = 0.0f; s[b] = 0.0f; }

    const int stride = gridDim.x * blockDim.x;
    for (int i = blockIdx.x * blockDim.x + threadIdx.x; i < n4; i += stride) {
        const int e = i << 2;                  // element index (multiple of 4)
        const int bb = e >> HW_BITS;           // batch
        const int r  = e & (HW - 1);           // offset within plane
        const int tbase = ((bb * 3) << HW_BITS) + r;

        const float4 p4  = __ldg((const float4*)(pred + e));
        const float4 h4  = __ldg((const float4*)(target + tbase));            // hm
        const float4 v4  = __ldg((const float4*)(target + tbase + HW));       // valid
        const float4 q4  = __ldg((const float4*)(target + tbase + 2 * HW));   // pos

        const float pr[4] = { p4.x, p4.y, p4.z, p4.w };
        const float hm[4] = { h4.x, h4.y, h4.z, h4.w };
        const float vd[4] = { v4.x, v4.y, v4.z, v4.w };
        const float ps[4] = { q4.x, q4.y, q4.z, q4.w };

#pragma unroll
        for (int j = 0; j < 4; j++) {
            const bool valid = vd[j] > 0.0f;
            const bool pos   = ps[j] > 0.0f;   // pos implies valid in the data
            const float p    = pr[j];
            const float omp  = 1.0f - p;
            const float g    = pos ? omp : p;          // |pred - pos_ind| for valid
            const float la   = pos ? p : omp;          // log argument
            const float lg   = __logf(la);
            const float d    = 1.0f - hm[j];
            const float d2   = d * d;
            const float nw   = d2 * d2;                // (1-hm)^4
            const float val  = pos ? lg : lg * nw;
            // bin index; idx=NBINS for invalid -> no accumulator matches
            int idx = valid ? min((int)(g * 10.0f), NBINS - 1) : NBINS;
#pragma unroll
            for (int b = 0; b < NBINS; b++) {
                if (idx == b) { cnt[b] += 1.0f; s[b] += val; }
            }
        }
    }

    // warp reduction
#pragma unroll
    for (int b = 0; b < NBINS; b++) {
#pragma unroll
        for (int o = 16; o > 0; o >>= 1) {
            cnt[b] += __shfl_down_sync(0xFFFFFFFFu, cnt[b], o);
            s[b]   += __shfl_down_sync(0xFFFFFFFFu, s[b], o);
        }
    }

    __shared__ float sc[NBINS];
    __shared__ float ss[NBINS];
    if (threadIdx.x < NBINS) { sc[threadIdx.x] = 0.0f; ss[threadIdx.x] = 0.0f; }
    __syncthreads();

    if ((threadIdx.x & 31) == 0) {
#pragma unroll
        for (int b = 0; b < NBINS; b++) {
            atomicAdd(&sc[b], cnt[b]);
            atomicAdd(&ss[b], s[b]);
        }
    }
    __syncthreads();

    if (threadIdx.x < NBINS) {
        atomicAdd(&g_cnt[threadIdx.x], sc[threadIdx.x]);
        atomicAdd(&g_sum[threadIdx.x], ss[threadIdx.x]);
    }
}

__global__ void ghm_final_kernel(float* __restrict__ out) {
    if (threadIdx.x == 0) {
        float tot = 0.0f;
        int nn = 0;
#pragma unroll
        for (int b = 0; b < NBINS; b++) {
            tot += g_cnt[b];
            if (g_cnt[b] > 0.0f) nn++;
        }
        tot = fmaxf(tot, 1.0f);
        const float nnf = fmaxf((float)nn, 1.0f);
        float acc = 0.0f;
#pragma unroll
        for (int b = 0; b < NBINS; b++) {
            float w = (g_cnt[b] > 0.0f) ? (tot / fmaxf(g_cnt[b], 1.0f)) : 0.0f;
            w /= nnf;
            acc += w * g_sum[b];
        }
        out[0] = -acc / tot;
    }
}

extern "C" void kernel_launch(void* const* d_in, const int* in_sizes, int n_in,
                              void* d_out, int out_size) {
    const float* pred   = (const float*)d_in[0];
    const float* target = (const float*)d_in[1];
    float* out = (float*)d_out;

    const int n  = in_sizes[0];      // 32*512*512 = 8388608
    const int n4 = n >> 2;

    ghm_zero_kernel<<<1, 32>>>();

    const int threads = 256;
    const int blocks  = 1184;        // 148 SMs * 8 blocks, grid-stride covers n4
    ghm_main_kernel<<<blocks, threads>>>(pred, target, n4);

    ghm_final_kernel<<<1, 32>>>(out);
}

// round 2
// speedup vs baseline: 2.8614x; 2.8614x over previous
#include <cuda_runtime.h>
#include <cuda_bf16.h>

// GHM-C loss, single-pass formulation.
// loss = -(sum_b w[b]*S[b]) / tot
//   count[b] = #valid elements with bin(g)==b          (g = |pred - pos|)
//   S[b]     = sum over those elements of (pos ? log(pred) : log(1-pred)*(1-hm)^4)
//   tot      = max(sum_b count[b], 1)
//   w[b]     = (count[b]>0 ? tot/max(count[b],1) : 0) / max(#nonempty bins, 1)
//
// R1 optimizations:
//  - per-bin counts packed 6-bit x5 into two int registers (max 28/bin/thread)
//  - per-bin sums in lane-sliced smem [warp][bin][lane] -> bank == lane,
//    conflict-free accumulate: LDS+FADD+STS instead of 10x predicated FADD
//  - final kernel re-zeros the device globals (invariant: zero at entry),
//    eliminating the separate zero kernel

#define HW_BITS 18          // 512*512 = 2^18
#define HW (1 << HW_BITS)
#define NBINS 10
#define NWARPS 8            // 256 threads
#define GRID_BLOCKS 1184    // fixed: bounds per-thread elems to 28 (< 63 for 6-bit packing)

__device__ float g_cnt[NBINS];
__device__ float g_sum[NBINS];

__global__ __launch_bounds__(256) void ghm_main_kernel(
    const float* __restrict__ pred,
    const float* __restrict__ target,
    int n4)   // number of float4 groups (n/4)
{
    __shared__ float s_smem[NWARPS][NBINS][32];   // lane-sliced per-warp sums
    __shared__ float sb_sum[NBINS];
    __shared__ float sb_cnt[NBINS];

    const int tid  = threadIdx.x;
    const int warp = tid >> 5;
    const int lane = tid & 31;

    // zero smem
    #pragma unroll
    for (int b = 0; b < NBINS; b++) s_smem[warp][b][lane] = 0.0f;
    if (tid < NBINS) { sb_sum[tid] = 0.0f; sb_cnt[tid] = 0.0f; }
    __syncthreads();

    unsigned cnt_lo = 0u, cnt_hi = 0u;   // bins 0-4 / 5-9, 6 bits each
    float* myrow = &s_smem[warp][0][lane];  // stride 32 floats per bin

    const int stride = gridDim.x * blockDim.x;
    for (int i = blockIdx.x * blockDim.x + tid; i < n4; i += stride) {
        const int e = i << 2;                  // element index (multiple of 4)
        const int bb = e >> HW_BITS;           // batch
        const int r  = e & (HW - 1);           // offset within plane
        const int tbase = ((bb * 3) << HW_BITS) + r;

        const float4 p4 = __ldg((const float4*)(pred + e));
        const float4 h4 = __ldg((const float4*)(target + tbase));            // hm
        const float4 v4 = __ldg((const float4*)(target + tbase + HW));       // valid
        const float4 q4 = __ldg((const float4*)(target + tbase + 2 * HW));   // pos

        const float pr[4] = { p4.x, p4.y, p4.z, p4.w };
        const float hm[4] = { h4.x, h4.y, h4.z, h4.w };
        const float vd[4] = { v4.x, v4.y, v4.z, v4.w };
        const float ps[4] = { q4.x, q4.y, q4.z, q4.w };

        #pragma unroll
        for (int j = 0; j < 4; j++) {
            const bool pos  = ps[j] > 0.0f;        // pos implies valid in the data
            const float p   = pr[j];
            const float omp = 1.0f - p;
            const float g   = pos ? omp : p;       // |pred - pos_ind| when valid
            const float la  = pos ? p : omp;       // log argument
            const float lg  = __logf(la);
            const float d   = 1.0f - hm[j];
            const float d2  = d * d;
            const float nw  = d2 * d2;             // (1-hm)^4
            // vd[j] is exactly 1.0 or 0.0 -> multiply masks invalid to 0
            const float val = (pos ? lg : lg * nw) * vd[j];

            const int idx = min((int)(g * 10.0f), NBINS - 1);   // 0..9

            // sum accumulate: lane-sliced smem, bank == lane, conflict-free
            myrow[idx * 32] += val;

            // count accumulate: packed 6-bit fields, masked by valid
            const bool hi = idx >= 5;
            const unsigned sh = (unsigned)(hi ? (idx - 5) : idx) * 6u;
            const unsigned inc = (vd[j] > 0.0f) ? (1u << sh) : 0u;
            if (hi) cnt_hi += inc; else cnt_lo += inc;
        }
    }

    // ---- reduce counts: unpack, warp-shuffle, smem atomics ----
    #pragma unroll
    for (int b = 0; b < NBINS; b++) {
        unsigned c = ((b < 5 ? cnt_lo : cnt_hi) >> (6 * (b < 5 ? b : b - 5))) & 63u;
        #pragma unroll
        for (int o = 16; o > 0; o >>= 1)
            c += __shfl_down_sync(0xFFFFFFFFu, c, o);
        if (lane == 0) atomicAdd(&sb_cnt[b], (float)c);
    }

    __syncthreads();

    // ---- reduce sums: 80 threads, one per (warp, bin), 32 lanes each ----
    if (tid < NWARPS * NBINS) {
        const int w = tid / NBINS;
        const int b = tid % NBINS;
        float acc = 0.0f;
        #pragma unroll
        for (int l = 0; l < 32; l++) acc += s_smem[w][b][l];
        atomicAdd(&sb_sum[b], acc);
    }
    __syncthreads();

    if (tid < NBINS) {
        atomicAdd(&g_sum[tid], sb_sum[tid]);
        atomicAdd(&g_cnt[tid], sb_cnt[tid]);
    }
}

__global__ void ghm_final_kernel(float* __restrict__ out) {
    if (threadIdx.x == 0) {
        float tot = 0.0f;
        int nn = 0;
        #pragma unroll
        for (int b = 0; b < NBINS; b++) {
            tot += g_cnt[b];
            if (g_cnt[b] > 0.0f) nn++;
        }
        tot = fmaxf(tot, 1.0f);
        const float nnf = fmaxf((float)nn, 1.0f);
        float acc = 0.0f;
        #pragma unroll
        for (int b = 0; b < NBINS; b++) {
            float w = (g_cnt[b] > 0.0f) ? (tot / fmaxf(g_cnt[b], 1.0f)) : 0.0f;
            acc += (w / nnf) * g_sum[b];
        }
        out[0] = -acc / tot;
    }
    // re-zero globals for the next graph replay (invariant: zero at kernel_launch entry)
    if (threadIdx.x < NBINS) {
        g_cnt[threadIdx.x] = 0.0f;
        g_sum[threadIdx.x] = 0.0f;
    }
}

extern "C" void kernel_launch(void* const* d_in, const int* in_sizes, int n_in,
                              void* d_out, int out_size) {
    const float* pred   = (const float*)d_in[0];
    const float* target = (const float*)d_in[1];
    float* out = (float*)d_out;

    const int n  = in_sizes[0];      // 32*512*512 = 8388608
    const int n4 = n >> 2;

    ghm_main_kernel<<<GRID_BLOCKS, 256>>>(pred, target, n4);
    ghm_final_kernel<<<1, 32>>>(out);
}